// round 14
// baseline (speedup 1.0000x reference)
#include <cuda_runtime.h>
#include <cuda_bf16.h>
#include <math.h>

#define SIZE   512
#define N_PHOS 256
#define H      10
#define THRESH 0.05f

#define MAX_TW  73       // max intermediate width (+1 pad)
#define STRIPS  4
#define STRIP_H 13       // 4*13 = 52 >= max tile height
#define NTASKS  (N_PHOS * STRIPS)

#define NBLOCKS  128
#define NTHREADS 512
#define NGROUPS  4                                // 128-thread worker groups
#define PX_PER_BLOCK ((SIZE * SIZE) / NBLOCKS)    // 2048 -> one float4/thread

// Self-restoring scratch accumulator: zero at module load; phase D re-zeros
// it every run, so it is zero at every kernel entry (replay-deterministic).
__device__ __align__(16) float g_scratch[SIZE * SIZE];

__device__ int      g_max_bits  = 0;
__device__ unsigned g_bar_count = 0;
__device__ unsigned g_bar_gen   = 0;
__device__ unsigned g_task_ctr  = 0;   // reset after barrier 1 each run

static __device__ __forceinline__ int refl(int i) {
    if (i < 0)        i = -i;
    if (i > SIZE - 1) i = 2 * (SIZE - 1) - i;
    return i;
}

// Named barrier over one 128-thread group (ids 1..4; 0 is __syncthreads).
#define GBAR(g) asm volatile("bar.sync %0, 128;" :: "r"((g) + 1) : "memory")

// Sense-reversing software grid barrier; 128 blocks, 1/SM, all co-resident.
static __device__ __forceinline__ void grid_barrier() {
    __syncthreads();
    if (threadIdx.x == 0) {
        unsigned my_gen = *((volatile unsigned*)&g_bar_gen);
        __threadfence();
        unsigned arrived = atomicAdd(&g_bar_count, 1u);
        if (arrived == NBLOCKS - 1) {
            atomicExch(&g_bar_count, 0u);
            __threadfence();
            atomicExch(&g_bar_gen, my_gen + 1u);
        } else {
            while (*((volatile unsigned*)&g_bar_gen) == my_gen) { __nanosleep(32); }
        }
        __threadfence();
    }
    __syncthreads();
}

// Interval sum of taps dy in [a,b] (clamped to [-H,H]) from prefix weights.
static __device__ __forceinline__ float ivsum(int a, int b, const float* __restrict__ cw2) {
    a = max(a, -H);
    b = min(b,  H);
    return (a <= b) ? (cw2[b + H + 1] - cw2[a + H]) : 0.0f;
}

__global__ __launch_bounds__(NTHREADS, 1) void k_fused(
    const float* __restrict__ phoscoding,
    const float* __restrict__ grid,
    float* __restrict__ img)
{
    const int tid = threadIdx.x;
    const int grp = tid >> 7;          // 0..3
    const int gl  = tid & 127;         // lane within group

    __shared__ float    sw [NGROUPS][2 * H + 1];
    __shared__ float    scw[NGROUPS][2 * H + 2];
    __shared__ short    sLo[NGROUPS][MAX_TW];
    __shared__ short    sHi[NGROUPS][MAX_TW];
    __shared__ float    st [NGROUPS][STRIP_H][MAX_TW];
    __shared__ unsigned s_task[NGROUPS];
    __shared__ float    smax[16];

    if (blockIdx.x == 0 && tid == 0) g_max_bits = 0;

    // =================== Phase B: task-queue scatter ===================
    for (;;) {
        if (gl == 0) s_task[grp] = atomicAdd(&g_task_ctr, 1u);
        GBAR(grp);                                   // also end-of-prev-task fence
        const unsigned tsk = s_task[grp];
        if (tsk >= NTASKS) break;

        const int p = (int)(tsk >> 2);
        const int s = (int)(tsk & 3u);

        const float bright = phoscoding[p];
        const float x = grid[3 * p + 0];
        const float y = grid[3 * p + 1];
        const float r = grid[3 * p + 2];

        const float sigma = r / 3.0f;
        const float half  = ceilf(2.0f * sigma);
        const float r2    = __fmul_rn(r, r);
        const float cx = x - 1.0f, cy = y - 1.0f;

        const int oy0 = max(0,        (int)floorf(cy - r) - H);
        const int oy1 = min(SIZE - 1, (int)ceilf (cy + r) + H);
        const int ox0 = max(0,        (int)floorf(cx - r) - H);
        const int ox1 = min(SIZE - 1, (int)ceilf (cx + r) + H);
        const int cLo = max(0,        ox0 - H);
        const int cHi = min(SIZE - 1, ox1 + H);

        int ow = ox1 - ox0 + 1;                      // <= 52
        int tw = cHi - cLo + 1;                      // <= 72
        if (tw > MAX_TW) tw = MAX_TW;

        const int row0  = oy0 + s * STRIP_H;
        const int row1  = min(row0 + STRIP_H, oy1 + 1);
        const int nrows = row1 - row0;               // may be <= 0

        // Weights + prefix: warp 0 of the group only (no extra named barrier)
        if (gl < 32) {
            if (gl < 2 * H + 1) {
                float pos = (float)(gl - H);
                float q   = pos / sigma;
                float v   = expf(-0.5f * (q * q));
                sw[grp][gl] = (fabsf(pos) <= half) ? v : 0.0f;
            }
            __syncwarp();
            if (gl == 0) {
                float acc = 0.0f;
                scw[grp][0] = 0.0f;
                #pragma unroll
                for (int k = 0; k < 2 * H + 1; k++) { acc += sw[grp][k]; scw[grp][k + 1] = acc; }
            }
        }

        // Per-column disk row-interval [mLo, mHi] with exact reference
        // rounding: rn(dx2 + rn(dyc*dyc)) <= rn(r*r).
        if (gl < tw) {
            int   col = cLo + gl;
            float dxc = (float)(col + 1) - x;
            float dx2 = __fmul_rn(dxc, dxc);
            int lo = 512, hi = -512;
            if (dx2 <= r2) {
                float hy = sqrtf(fmaxf(r2 - dx2, 0.0f));
                lo = (int)ceilf (y - hy) - 1;
                hi = (int)floorf(y + hy) - 1;
                #pragma unroll
                for (int k = 0; k < 2; k++) {
                    float d = (float)(lo) - y;
                    if (__fadd_rn(dx2, __fmul_rn(d, d)) <= r2) lo--;
                }
                #pragma unroll
                for (int k = 0; k < 2; k++) {
                    float d = (float)(lo + 1) - y;
                    if (!(__fadd_rn(dx2, __fmul_rn(d, d)) <= r2)) lo++;
                }
                #pragma unroll
                for (int k = 0; k < 2; k++) {
                    float d = (float)(hi + 2) - y;
                    if (__fadd_rn(dx2, __fmul_rn(d, d)) <= r2) hi++;
                }
                #pragma unroll
                for (int k = 0; k < 2; k++) {
                    float d = (float)(hi + 1) - y;
                    if (!(__fadd_rn(dx2, __fmul_rn(d, d)) <= r2)) hi--;
                }
                if (lo > hi) { lo = 512; hi = -512; }
            }
            sLo[grp][gl] = (short)lo;
            sHi[grp][gl] = (short)hi;
        }
        GBAR(grp);

        // Vertical: prefix-sum interval differences, O(1)/point (+2 refl terms)
        if (nrows > 0) {
            const float* cwp = scw[grp];
            const int pts = nrows * tw;
            const unsigned recip = (1u << 20) / (unsigned)tw + 1u;  // exact: pts < 2^20/tw
            for (int idx = gl; idx < pts; idx += 128) {
                int i   = (int)(((unsigned)idx * recip) >> 20);
                int c   = idx - i * tw;
                int row = row0 + i;
                int lo  = sLo[grp][c];
                int hi  = sHi[grp][c];
                st[grp][i][c] = ivsum(lo - row,        hi - row,        cwp)
                              + ivsum(-hi - row,       -lo - row,       cwp)
                              + ivsum(1022 - hi - row, 1022 - lo - row, cwp);
            }
        }
        GBAR(grp);

        // Horizontal 21-tap blur + threshold + atomic scatter
        if (nrows > 0) {
            const float wsum  = scw[grp][2 * H + 1];
            const float scale = bright / (wsum * wsum);
            const bool interior = (ox0 >= H) && (ox1 <= SIZE - 1 - H);
            const int pts = nrows * ow;
            const unsigned recip = (1u << 20) / (unsigned)ow + 1u;
            for (int idx = gl; idx < pts; idx += 128) {
                int i   = (int)(((unsigned)idx * recip) >> 20);
                int j   = idx - i * ow;
                int col = ox0 + j;
                float acc = 0.0f;
                if (interior) {
                    const float* trow = &st[grp][i][col - cLo - H];
                    #pragma unroll
                    for (int k = 0; k < 2 * H + 1; k++)
                        acc = fmaf(sw[grp][k], trow[k], acc);
                } else {
                    #pragma unroll
                    for (int dx = -H; dx <= H; dx++) {
                        int cc = refl(col + dx) - cLo;
                        acc = fmaf(sw[grp][dx + H], st[grp][i][cc], acc);
                    }
                }
                float val = acc * scale;
                if (val >= THRESH)
                    atomicAdd(&g_scratch[(row0 + i) * SIZE + col], val);
            }
        }
        // next-iteration pop GBAR doubles as the end-of-task fence
    }

    grid_barrier();   // all scatters complete; g_max_bits reset visible

    // Reset task counter for the next replay (ordered after all pops).
    if (blockIdx.x == 0 && tid == 0) g_task_ctr = 0;

    // ------- Phase C: load + clamp (keep in regs), reduce global max -------
    const int base = blockIdx.x * PX_PER_BLOCK + tid * 4;
    float4 v4 = __ldcg(reinterpret_cast<const float4*>(g_scratch + base));
    v4.x = fminf(v4.x, 1.f); v4.y = fminf(v4.y, 1.f);
    v4.z = fminf(v4.z, 1.f); v4.w = fminf(v4.w, 1.f);
    {
        float v = fmaxf(fmaxf(v4.x, v4.y), fmaxf(v4.z, v4.w));
        #pragma unroll
        for (int off = 16; off > 0; off >>= 1)
            v = fmaxf(v, __shfl_xor_sync(0xffffffffu, v, off));
        int lane = tid & 31, wid = tid >> 5;
        if (lane == 0) smax[wid] = v;
        __syncthreads();
        if (wid == 0) {
            v = (lane < (NTHREADS >> 5)) ? smax[lane] : 0.0f;
            #pragma unroll
            for (int off = 8; off > 0; off >>= 1)
                v = fmaxf(v, __shfl_xor_sync(0xffffffffu, v, off));
            if (lane == 0) atomicMax(&g_max_bits, __float_as_int(v));
        }
    }

    grid_barrier();   // global max final

    // ---- Phase D: normalize regs -> d_out; re-zero scratch for next run ----
    {
        float m = __int_as_float(__ldcg(&g_max_bits));
        if (m > 0.0f) { v4.x /= m; v4.y /= m; v4.z /= m; v4.w /= m; }
        *reinterpret_cast<float4*>(img + base) = v4;
        *reinterpret_cast<float4*>(g_scratch + base) = make_float4(0.f, 0.f, 0.f, 0.f);
    }
}

extern "C" void kernel_launch(void* const* d_in, const int* in_sizes, int n_in,
                              void* d_out, int out_size) {
    const float* phos = (const float*)d_in[0];
    const float* grid = (const float*)d_in[1];
    if (n_in >= 2 && in_sizes[0] == 3 * N_PHOS && in_sizes[1] == N_PHOS) {
        const float* tmp = phos; phos = grid; grid = tmp;
    }
    float* img = (float*)d_out;

    k_fused<<<NBLOCKS, NTHREADS>>>(phos, grid, img);
}

// round 15
// speedup vs baseline: 1.1152x; 1.1152x over previous
#include <cuda_runtime.h>
#include <cuda_bf16.h>
#include <math.h>

#define SIZE   512
#define N_PHOS 256
#define H      10
#define THRESH 0.05f

#define MAX_OH 52        // disk span (<=31) + 2H + 1
#define MAX_TW 73        // MAX_OH + 2H (+1 pad)

#define NBLOCKS  128                 // one block per SM; 2 phosphenes each
#define NTHREADS 512
#define PX_PER_BLOCK ((SIZE * SIZE) / NBLOCKS)   // 2048 -> one float4 / thread

// Self-restoring scratch accumulator: zero at module load; phase D re-zeros
// it every run, so it is zero at every kernel entry (replay-deterministic).
__device__ __align__(16) float g_scratch[SIZE * SIZE];

__device__ int      g_max_bits  = 0;
__device__ unsigned g_bar_count = 0;
__device__ unsigned g_bar_gen   = 0;

static __device__ __forceinline__ int refl(int i) {
    if (i < 0)        i = -i;
    if (i > SIZE - 1) i = 2 * (SIZE - 1) - i;
    return i;
}

// Sense-reversing software grid barrier; 128 blocks, 1/SM, all co-resident.
static __device__ __forceinline__ void grid_barrier() {
    __syncthreads();
    if (threadIdx.x == 0) {
        unsigned my_gen = *((volatile unsigned*)&g_bar_gen);
        __threadfence();
        unsigned arrived = atomicAdd(&g_bar_count, 1u);
        if (arrived == NBLOCKS - 1) {
            atomicExch(&g_bar_count, 0u);
            __threadfence();
            atomicExch(&g_bar_gen, my_gen + 1u);
        } else {
            while (*((volatile unsigned*)&g_bar_gen) == my_gen) { __nanosleep(32); }
        }
        __threadfence();
    }
    __syncthreads();
}

// Interval sum of taps dy in [a,b] (clamped to [-H,H]) from prefix weights.
static __device__ __forceinline__ float ivsum(int a, int b, const float* __restrict__ cw2) {
    a = max(a, -H);
    b = min(b,  H);
    return (a <= b) ? (cw2[b + H + 1] - cw2[a + H]) : 0.0f;
}

__global__ __launch_bounds__(NTHREADS, 1) void k_fused(
    const float* __restrict__ phoscoding,
    const float* __restrict__ grid,
    float* __restrict__ img)
{
    const int tid  = threadIdx.x;
    const int sub  = tid >> 8;                    // 0/1: which phosphene half
    const int l    = tid & 255;                   // lane within half-block
    const int p    = (blockIdx.x << 1) + sub;     // phosphene id

    __shared__ float w[2][2 * H + 1];
    __shared__ float cw2[2][2 * H + 2];
    __shared__ short s_mLo[2][MAX_TW], s_mHi[2][MAX_TW];
    __shared__ float t[2][MAX_OH][MAX_TW];
    __shared__ float smax[16];

    if (blockIdx.x == 0 && tid == 0) g_max_bits = 0;

    // ---- phosphene params + tile geometry ----
    const float bright = phoscoding[p];
    const float x = grid[3 * p + 0];
    const float y = grid[3 * p + 1];
    const float r = grid[3 * p + 2];

    const float sigma = r / 3.0f;
    const float half  = ceilf(2.0f * sigma);
    const float r2    = __fmul_rn(r, r);

    const float cx = x - 1.0f, cy = y - 1.0f;   // 0-based center

    const int oy0 = max(0,        (int)floorf(cy - r) - H);
    const int oy1 = min(SIZE - 1, (int)ceilf (cy + r) + H);
    const int ox0 = max(0,        (int)floorf(cx - r) - H);
    const int ox1 = min(SIZE - 1, (int)ceilf (cx + r) + H);

    const int cLo = max(0,        ox0 - H);
    const int cHi = min(SIZE - 1, ox1 + H);

    int oh = oy1 - oy0 + 1;          // <= 52
    int ow = ox1 - ox0 + 1;          // <= 52
    int tw = cHi - cLo + 1;          // <= 72
    if (oh > MAX_OH) oh = MAX_OH;
    if (tw > MAX_TW) tw = MAX_TW;

    // Blur weights + prefix scan: one warp per half, shfl inclusive scan.
    if (l < 32) {
        float pos = (float)(l - H);
        float q   = pos / sigma;
        float v   = (l < 2 * H + 1 && fabsf(pos) <= half)
                    ? expf(-0.5f * (q * q)) : 0.0f;
        float s = v;
        #pragma unroll
        for (int off = 1; off < 32; off <<= 1) {
            float u = __shfl_up_sync(0xffffffffu, s, off);
            if (l >= off) s += u;
        }
        if (l < 2 * H + 1) {
            w[sub][l]       = v;
            cw2[sub][l + 1] = s;
        }
        if (l == 0) cw2[sub][0] = 0.0f;
    }

    // Per-column disk row-interval [mLo, mHi] (lanes 0..tw-1).
    // Exact predicate matches reference rounding: rn(dx2 + rn(dyc*dyc)) <= rn(r*r).
    if (l < tw) {
        int   col = cLo + l;
        float dxc = (float)(col + 1) - x;
        float dx2 = __fmul_rn(dxc, dxc);
        int lo = 512, hi = -512;                 // empty sentinel
        if (dx2 <= r2) {
            float hy = sqrtf(fmaxf(r2 - dx2, 0.0f));
            lo = (int)ceilf (y - hy) - 1;
            hi = (int)floorf(y + hy) - 1;
            #pragma unroll
            for (int k = 0; k < 2; k++) {
                float d = (float)(lo) - y;
                if (__fadd_rn(dx2, __fmul_rn(d, d)) <= r2) lo--;
            }
            #pragma unroll
            for (int k = 0; k < 2; k++) {
                float d = (float)(lo + 1) - y;
                if (!(__fadd_rn(dx2, __fmul_rn(d, d)) <= r2)) lo++;
            }
            #pragma unroll
            for (int k = 0; k < 2; k++) {
                float d = (float)(hi + 2) - y;
                if (__fadd_rn(dx2, __fmul_rn(d, d)) <= r2) hi++;
            }
            #pragma unroll
            for (int k = 0; k < 2; k++) {
                float d = (float)(hi + 1) - y;
                if (!(__fadd_rn(dx2, __fmul_rn(d, d)) <= r2)) hi--;
            }
            if (lo > hi) { lo = 512; hi = -512; }
        }
        s_mLo[sub][l] = (short)lo;
        s_mHi[sub][l] = (short)hi;
    }
    __syncthreads();

    // ---------------- Phase B: scatter into g_scratch ----------------
    {
        const float* cwp = cw2[sub];
        // Vertical: prefix-sum interval differences, O(1)/point (+2 refl
        // terms). Exact i = idx / tw via magic reciprocal (k=22 is exact:
        // recip*tw - 2^22 <= 72 << 2^22 / 3744).
        const int pts_v = oh * tw;                        // <= 3744
        const unsigned recip_v = (1u << 22) / (unsigned)tw + 1u;
        for (int idx = l; idx < pts_v; idx += 256) {
            int i   = (int)(((unsigned)idx * recip_v) >> 22);
            int c   = idx - i * tw;
            int row = oy0 + i;
            int lo  = s_mLo[sub][c];
            int hi  = s_mHi[sub][c];
            t[sub][i][c] = ivsum(lo - row,        hi - row,        cwp)
                         + ivsum(-hi - row,       -lo - row,       cwp)
                         + ivsum(1022 - hi - row, 1022 - lo - row, cwp);
        }
        __syncthreads();

        // Horizontal 21-tap blur (3 independent accumulator chains)
        // + threshold + atomic scatter.
        const float wsum  = cwp[2 * H + 1];
        const float scale = bright / (wsum * wsum);
        const bool interior = (ox0 >= H) && (ox1 <= SIZE - 1 - H);
        const int pts_h = oh * ow;                        // <= 2704
        const unsigned recip_h = (1u << 22) / (unsigned)ow + 1u;
        for (int idx = l; idx < pts_h; idx += 256) {
            int i   = (int)(((unsigned)idx * recip_h) >> 22);
            int j   = idx - i * ow;
            int col = ox0 + j;
            float acc;
            if (interior) {
                const float* trow = &t[sub][i][col - cLo - H];
                float a0 = 0.f, a1 = 0.f, a2 = 0.f;
                #pragma unroll
                for (int k = 0; k < 7; k++) {
                    a0 = fmaf(w[sub][3 * k + 0], trow[3 * k + 0], a0);
                    a1 = fmaf(w[sub][3 * k + 1], trow[3 * k + 1], a1);
                    a2 = fmaf(w[sub][3 * k + 2], trow[3 * k + 2], a2);
                }
                acc = a0 + a1 + a2;
            } else {
                float a0 = 0.f;
                #pragma unroll
                for (int dx = -H; dx <= H; dx++) {
                    int cc = refl(col + dx) - cLo;
                    a0 = fmaf(w[sub][dx + H], t[sub][i][cc], a0);
                }
                acc = a0;
            }
            float val = acc * scale;
            if (val >= THRESH)
                atomicAdd(&g_scratch[(oy0 + i) * SIZE + col], val);
        }
    }

    grid_barrier();   // all scatters complete; g_max_bits reset visible

    // ------- Phase C: load + clamp (keep in regs), reduce global max -------
    const int base = blockIdx.x * PX_PER_BLOCK + tid * 4;
    float4 v4 = __ldcg(reinterpret_cast<const float4*>(g_scratch + base));
    v4.x = fminf(v4.x, 1.f); v4.y = fminf(v4.y, 1.f);
    v4.z = fminf(v4.z, 1.f); v4.w = fminf(v4.w, 1.f);
    {
        float v = fmaxf(fmaxf(v4.x, v4.y), fmaxf(v4.z, v4.w));
        #pragma unroll
        for (int off = 16; off > 0; off >>= 1)
            v = fmaxf(v, __shfl_xor_sync(0xffffffffu, v, off));
        int lane = tid & 31, wid = tid >> 5;
        if (lane == 0) smax[wid] = v;
        __syncthreads();
        if (wid == 0) {
            v = (lane < (NTHREADS >> 5)) ? smax[lane] : 0.0f;
            #pragma unroll
            for (int off = 8; off > 0; off >>= 1)
                v = fmaxf(v, __shfl_xor_sync(0xffffffffu, v, off));
            if (lane == 0) atomicMax(&g_max_bits, __float_as_int(v));
        }
    }

    grid_barrier();   // global max final

    // ---- Phase D: normalize regs -> d_out; re-zero scratch for next run ----
    {
        float m = __int_as_float(__ldcg(&g_max_bits));
        if (m > 0.0f) { v4.x /= m; v4.y /= m; v4.z /= m; v4.w /= m; }
        *reinterpret_cast<float4*>(img + base) = v4;
        *reinterpret_cast<float4*>(g_scratch + base) = make_float4(0.f, 0.f, 0.f, 0.f);
    }
}

extern "C" void kernel_launch(void* const* d_in, const int* in_sizes, int n_in,
                              void* d_out, int out_size) {
    const float* phos = (const float*)d_in[0];
    const float* grid = (const float*)d_in[1];
    if (n_in >= 2 && in_sizes[0] == 3 * N_PHOS && in_sizes[1] == N_PHOS) {
        const float* tmp = phos; phos = grid; grid = tmp;
    }
    float* img = (float*)d_out;

    k_fused<<<NBLOCKS, NTHREADS>>>(phos, grid, img);
}

// round 16
// speedup vs baseline: 1.2284x; 1.1015x over previous
#include <cuda_runtime.h>
#include <cuda_bf16.h>
#include <math.h>

#define SIZE   512
#define N_PHOS 256
#define H      10
#define THRESH 0.05f

#define MAX_OH 52        // disk span (<=31) + 2H + 1
#define MAX_TW 73        // MAX_OH + 2H (+1 pad)

#define NBLOCKS  128                 // one block per SM; 2 phosphenes each
#define NTHREADS 1024                // 512 threads per phosphene
#define PX_PER_BLOCK ((SIZE * SIZE) / NBLOCKS)   // 2048 -> one float2 / thread

// Self-restoring scratch accumulator: zero at module load; phase D re-zeros
// it every run, so it is zero at every kernel entry (replay-deterministic).
__device__ __align__(16) float g_scratch[SIZE * SIZE];

__device__ int      g_max_bits  = 0;
__device__ unsigned g_bar_count = 0;
__device__ unsigned g_bar_gen   = 0;

static __device__ __forceinline__ int refl(int i) {
    if (i < 0)        i = -i;
    if (i > SIZE - 1) i = 2 * (SIZE - 1) - i;
    return i;
}

// Sense-reversing software grid barrier; 128 blocks, 1/SM, all co-resident.
static __device__ __forceinline__ void grid_barrier() {
    __syncthreads();
    if (threadIdx.x == 0) {
        unsigned my_gen = *((volatile unsigned*)&g_bar_gen);
        __threadfence();
        unsigned arrived = atomicAdd(&g_bar_count, 1u);
        if (arrived == NBLOCKS - 1) {
            atomicExch(&g_bar_count, 0u);
            __threadfence();
            atomicExch(&g_bar_gen, my_gen + 1u);
        } else {
            while (*((volatile unsigned*)&g_bar_gen) == my_gen) { __nanosleep(32); }
        }
        __threadfence();
    }
    __syncthreads();
}

// Interval sum of taps dy in [a,b] (clamped to [-H,H]) from prefix weights.
static __device__ __forceinline__ float ivsum(int a, int b, const float* __restrict__ cw2) {
    a = max(a, -H);
    b = min(b,  H);
    return (a <= b) ? (cw2[b + H + 1] - cw2[a + H]) : 0.0f;
}

__global__ __launch_bounds__(NTHREADS, 1) void k_fused(
    const float* __restrict__ phoscoding,
    const float* __restrict__ grid,
    float* __restrict__ img)
{
    const int tid  = threadIdx.x;
    const int sub  = tid >> 9;                    // 0/1: which phosphene half
    const int l    = tid & 511;                   // lane within half (512 thr)
    const int p    = (blockIdx.x << 1) + sub;     // phosphene id

    __shared__ float w[2][2 * H + 1];
    __shared__ float cw2[2][2 * H + 2];
    __shared__ short s_mLo[2][MAX_TW], s_mHi[2][MAX_TW];
    __shared__ float t[2][MAX_OH][MAX_TW];
    __shared__ float smax[32];

    if (blockIdx.x == 0 && tid == 0) g_max_bits = 0;

    // ---- phosphene params + tile geometry ----
    const float bright = phoscoding[p];
    const float x = grid[3 * p + 0];
    const float y = grid[3 * p + 1];
    const float r = grid[3 * p + 2];

    const float sigma = r / 3.0f;
    const float half  = ceilf(2.0f * sigma);
    const float r2    = __fmul_rn(r, r);

    const float cx = x - 1.0f, cy = y - 1.0f;   // 0-based center

    const int oy0 = max(0,        (int)floorf(cy - r) - H);
    const int oy1 = min(SIZE - 1, (int)ceilf (cy + r) + H);
    const int ox0 = max(0,        (int)floorf(cx - r) - H);
    const int ox1 = min(SIZE - 1, (int)ceilf (cx + r) + H);

    const int cLo = max(0,        ox0 - H);
    const int cHi = min(SIZE - 1, ox1 + H);

    int oh = oy1 - oy0 + 1;          // <= 52
    int ow = ox1 - ox0 + 1;          // <= 52
    int tw = cHi - cLo + 1;          // <= 72
    if (oh > MAX_OH) oh = MAX_OH;
    if (tw > MAX_TW) tw = MAX_TW;

    // Blur weights + prefix scan: one warp per half, shfl inclusive scan.
    if (l < 32) {
        float pos = (float)(l - H);
        float q   = pos / sigma;
        float v   = (l < 2 * H + 1 && fabsf(pos) <= half)
                    ? expf(-0.5f * (q * q)) : 0.0f;
        float s = v;
        #pragma unroll
        for (int off = 1; off < 32; off <<= 1) {
            float u = __shfl_up_sync(0xffffffffu, s, off);
            if (l >= off) s += u;
        }
        if (l < 2 * H + 1) {
            w[sub][l]       = v;
            cw2[sub][l + 1] = s;
        }
        if (l == 0) cw2[sub][0] = 0.0f;
    }

    // Per-column disk row-interval [mLo, mHi] (lanes 0..tw-1).
    // Exact predicate matches reference rounding: rn(dx2 + rn(dyc*dyc)) <= rn(r*r).
    if (l < tw) {
        int   col = cLo + l;
        float dxc = (float)(col + 1) - x;
        float dx2 = __fmul_rn(dxc, dxc);
        int lo = 512, hi = -512;                 // empty sentinel
        if (dx2 <= r2) {
            float hy = sqrtf(fmaxf(r2 - dx2, 0.0f));
            lo = (int)ceilf (y - hy) - 1;
            hi = (int)floorf(y + hy) - 1;
            #pragma unroll
            for (int k = 0; k < 2; k++) {
                float d = (float)(lo) - y;
                if (__fadd_rn(dx2, __fmul_rn(d, d)) <= r2) lo--;
            }
            #pragma unroll
            for (int k = 0; k < 2; k++) {
                float d = (float)(lo + 1) - y;
                if (!(__fadd_rn(dx2, __fmul_rn(d, d)) <= r2)) lo++;
            }
            #pragma unroll
            for (int k = 0; k < 2; k++) {
                float d = (float)(hi + 2) - y;
                if (__fadd_rn(dx2, __fmul_rn(d, d)) <= r2) hi++;
            }
            #pragma unroll
            for (int k = 0; k < 2; k++) {
                float d = (float)(hi + 1) - y;
                if (!(__fadd_rn(dx2, __fmul_rn(d, d)) <= r2)) hi--;
            }
            if (lo > hi) { lo = 512; hi = -512; }
        }
        s_mLo[sub][l] = (short)lo;
        s_mHi[sub][l] = (short)hi;
    }
    __syncthreads();

    // ---------------- Phase B: scatter into g_scratch ----------------
    {
        const float* cwp = cw2[sub];
        // Vertical: prefix-sum interval differences, O(1)/point (+2 refl
        // terms). Exact i = idx / tw via magic reciprocal (k=22 is exact
        // for idx < 3744 and 1 <= tw <= 73).
        const int pts_v = oh * tw;                        // <= 3744
        const unsigned recip_v = (1u << 22) / (unsigned)tw + 1u;
        for (int idx = l; idx < pts_v; idx += 512) {
            int i   = (int)(((unsigned)idx * recip_v) >> 22);
            int c   = idx - i * tw;
            int row = oy0 + i;
            int lo  = s_mLo[sub][c];
            int hi  = s_mHi[sub][c];
            t[sub][i][c] = ivsum(lo - row,        hi - row,        cwp)
                         + ivsum(-hi - row,       -lo - row,       cwp)
                         + ivsum(1022 - hi - row, 1022 - lo - row, cwp);
        }
        __syncthreads();

        // Horizontal 21-tap blur (3 independent accumulator chains)
        // + threshold + atomic scatter.
        const float wsum  = cwp[2 * H + 1];
        const float scale = bright / (wsum * wsum);
        const bool interior = (ox0 >= H) && (ox1 <= SIZE - 1 - H);
        const int pts_h = oh * ow;                        // <= 2704
        const unsigned recip_h = (1u << 22) / (unsigned)ow + 1u;
        for (int idx = l; idx < pts_h; idx += 512) {
            int i   = (int)(((unsigned)idx * recip_h) >> 22);
            int j   = idx - i * ow;
            int col = ox0 + j;
            float acc;
            if (interior) {
                const float* trow = &t[sub][i][col - cLo - H];
                float a0 = 0.f, a1 = 0.f, a2 = 0.f;
                #pragma unroll
                for (int k = 0; k < 7; k++) {
                    a0 = fmaf(w[sub][3 * k + 0], trow[3 * k + 0], a0);
                    a1 = fmaf(w[sub][3 * k + 1], trow[3 * k + 1], a1);
                    a2 = fmaf(w[sub][3 * k + 2], trow[3 * k + 2], a2);
                }
                acc = a0 + a1 + a2;
            } else {
                float a0 = 0.f;
                #pragma unroll
                for (int dx = -H; dx <= H; dx++) {
                    int cc = refl(col + dx) - cLo;
                    a0 = fmaf(w[sub][dx + H], t[sub][i][cc], a0);
                }
                acc = a0;
            }
            float val = acc * scale;
            if (val >= THRESH)
                atomicAdd(&g_scratch[(oy0 + i) * SIZE + col], val);
        }
    }

    grid_barrier();   // all scatters complete; g_max_bits reset visible

    // ------- Phase C: load + clamp (keep in regs), reduce global max -------
    const int base = blockIdx.x * PX_PER_BLOCK + tid * 2;
    float2 v2 = __ldcg(reinterpret_cast<const float2*>(g_scratch + base));
    v2.x = fminf(v2.x, 1.f); v2.y = fminf(v2.y, 1.f);
    {
        float v = fmaxf(v2.x, v2.y);
        #pragma unroll
        for (int off = 16; off > 0; off >>= 1)
            v = fmaxf(v, __shfl_xor_sync(0xffffffffu, v, off));
        int lane = tid & 31, wid = tid >> 5;
        if (lane == 0) smax[wid] = v;
        __syncthreads();
        if (wid == 0) {
            v = smax[lane];
            #pragma unroll
            for (int off = 16; off > 0; off >>= 1)
                v = fmaxf(v, __shfl_xor_sync(0xffffffffu, v, off));
            if (lane == 0) atomicMax(&g_max_bits, __float_as_int(v));
        }
    }

    grid_barrier();   // global max final

    // ---- Phase D: normalize regs -> d_out; re-zero scratch for next run ----
    {
        float m = __int_as_float(__ldcg(&g_max_bits));
        if (m > 0.0f) { v2.x /= m; v2.y /= m; }
        *reinterpret_cast<float2*>(img + base) = v2;
        *reinterpret_cast<float2*>(g_scratch + base) = make_float2(0.f, 0.f);
    }
}

extern "C" void kernel_launch(void* const* d_in, const int* in_sizes, int n_in,
                              void* d_out, int out_size) {
    const float* phos = (const float*)d_in[0];
    const float* grid = (const float*)d_in[1];
    if (n_in >= 2 && in_sizes[0] == 3 * N_PHOS && in_sizes[1] == N_PHOS) {
        const float* tmp = phos; phos = grid; grid = tmp;
    }
    float* img = (float*)d_out;

    k_fused<<<NBLOCKS, NTHREADS>>>(phos, grid, img);
}